// round 12
// baseline (speedup 1.0000x reference)
#include <cuda_runtime.h>
#include <cstdint>

typedef unsigned long long ull;

// ---------- packed f32x2 helpers ----------
__device__ __forceinline__ ull f2pack(float lo, float hi) {
    ull r; asm("mov.b64 %0,{%1,%2};" : "=l"(r) : "f"(lo), "f"(hi)); return r;
}
__device__ __forceinline__ void f2unpack(ull a, float& lo, float& hi) {
    asm("mov.b64 {%0,%1},%2;" : "=f"(lo), "=f"(hi) : "l"(a));
}
__device__ __forceinline__ ull f2mul(ull a, ull b) {
    ull r; asm("mul.rn.f32x2 %0,%1,%2;" : "=l"(r) : "l"(a), "l"(b)); return r;
}
__device__ __forceinline__ ull f2add(ull a, ull b) {
    ull r; asm("add.rn.f32x2 %0,%1,%2;" : "=l"(r) : "l"(a), "l"(b)); return r;
}
__device__ __forceinline__ ull f2fma(ull a, ull b, ull c) {
    ull r; asm("fma.rn.f32x2 %0,%1,%2,%3;" : "=l"(r) : "l"(a), "l"(b), "l"(c)); return r;
}

#define TW        32                    // tile width (pair cells); 512/32=16 exact
#define TH        64                    // tile height (output rows); 512/64=8 exact
#define IN_W      42                    // TW + 10
#define TOT_R     74                    // TH + 10 input rows
#define CHUNK     16
#define NCH       5                     // 16,16,16,16,10
#define IN_PITCH  104                   // ull per input row ({p,t} 16B cells, swizzled)
#define IN_ULL    (CHUNK * IN_PITCH)    // 1664
#define HB_PITCH  34                    // ull per hb row (8B cells, swizzled); 34 mod 16 = 2
#define SIG_STRIDE (CHUNK * HB_PITCH)   // 544
#define HBUF      (4 * SIG_STRIDE)      // 2176 per buffer
#define NPIX      12582912.0            // 48 * 512 * 512
#define NBLOCKS   3072                  // 16 x 8 x 24

// swizzles (conflict-free: h LDS.128 8-lane phases 5g mod 8 distinct;
// hb pitch 34 -> 2-row STS.64/LDS.64 16-lane phases tile mod 16 disjointly)
__device__ __forceinline__ int in_off(int x) { return 2 * x + 2 * (x >> 2); }
__device__ __forceinline__ int c_off(int c)  { return c + (c >> 4); }

// symmetric window: w[d] == w[10-d] (bit-exact on the recovered 1D window)
#define W(d) ws[(d) <= 5 ? (d) : 10 - (d)]

#define BAR_ALL()  asm volatile("bar.sync 0, 256;" ::: "memory")
#define BAR_CONS() asm volatile("bar.sync 1, 128;" ::: "memory")
#define BAR_PROD() asm volatile("bar.sync 2, 128;" ::: "memory")

__device__ double        g_acc  = 0.0;
__device__ unsigned int  g_done = 0u;

// ---- consumer: v shift-register consume + epilogue for one chunk ----
__device__ __forceinline__ void v_consume(ull* __restrict__ buf, ull acc[11],
                                          const ull ws[6], int vc, int vs, int ct,
                                          int cs, int nrows, float& lsum)
{
    const ull TWO  = f2pack(2.0f, 2.0f);
    const ull C1p  = f2pack(1e-4f, 1e-4f);
    const ull C2p  = f2pack(9e-4f, 9e-4f);
    const ull C12p = f2pack(1e-4f + 9e-4f, 1e-4f + 9e-4f);
    const ull EPSp = f2pack(1e-8f, 1e-8f);
    const ull SGN  = 0x8000000080000000ULL;

    // vertical consume: cell (vs, r, vc) read+written only by this thread
    {
        ull* hs = buf + vs * SIG_STRIDE + c_off(vc);
#pragma unroll
        for (int r = 0; r < CHUNK; r++) {
            if (r < nrows) {
                ull v = hs[r * HB_PITCH];
#pragma unroll
                for (int d = 10; d >= 1; d--) acc[d] = f2fma(v, W(d), acc[d - 1]);
                acc[0] = f2mul(v, W(0));
                if (cs + r >= 10)
                    hs[r * HB_PITCH] = acc[10];   // overlay into just-consumed slot
            }
        }
    }
    BAR_CONS();

    // epilogue: outputs e in [max(0,cs-10), cs+nrows-10), slot = e-cs+10
    {
        const int e0 = (cs >= 10) ? cs - 10 : 0;
        const int e1 = cs + nrows - 10;
        const int ntask = (e1 - e0) * TW;
        for (int t2 = ct; t2 < ntask; t2 += 128) {
            int e = e0 + (t2 >> 5);
            int c = t2 & 31;
            int base = (e - cs + 10) * HB_PITCH + c_off(c);
            ull bm1 = buf[0 * SIG_STRIDE + base];
            ull bm2 = buf[1 * SIG_STRIDE + base];
            ull bsq = buf[2 * SIG_STRIDE + base];
            ull bpt = buf[3 * SIG_STRIDE + base];
            ull m12   = f2mul(bm1, bm2);
            ull den1  = f2fma(bm1, bm1, f2fma(bm2, bm2, C1p));   // mu1^2+mu2^2+C1
            ull den2  = f2add(f2add(bsq, C12p), den1 ^ SGN);     // bsq - den1 + C1+C2
            ull sig12 = f2add(bpt, m12 ^ SGN);                   // bpt - m12
            ull num1  = f2fma(m12,   TWO, C1p);
            ull num2  = f2fma(sig12, TWO, C2p);
            ull num   = f2mul(num1, num2);
            ull den   = f2fma(den1, den2, EPSp);
            float n0, n1, d0, d1;
            f2unpack(num, n0, n1);
            f2unpack(den, d0, d1);
            lsum += __fdividef(n0, d0) + __fdividef(n1, d1);
        }
    }
}

// dynamic smem: inb[1664] | hb0[2176] | hb1[2176] = 6016 ull = 48128 B -> 4 CTAs/SM
__global__ __launch_bounds__(256, 4) void ssim_main_k(
    const float* __restrict__ pred,
    const float* __restrict__ targ,
    const float* __restrict__ win,
    float* __restrict__ out)
{
    extern __shared__ ull sm[];
    ull* inb = sm;
    ull* hbb[2] = { sm + IN_ULL, sm + IN_ULL + HBUF };

    const int tid  = threadIdx.x;
    const int lane = tid & 31;
    const int warp = tid >> 5;

    // --- recover separable symmetric 1D window: w1[j] = win[55+j]/rowsum ---
    float rowsum = 0.f;
#pragma unroll
    for (int j = 0; j < 11; j++) rowsum += __ldg(win + 55 + j);
    const float invr = 1.0f / rowsum;
    ull ws[6];
#pragma unroll
    for (int j = 0; j < 6; j++) {
        float w = __ldg(win + 55 + j) * invr;
        ws[j] = f2pack(w, w);
    }

    const int ox = blockIdx.x * TW;
    const int oy = blockIdx.y * TH;
    const int pz = blockIdx.z;                  // plane pair 0..23
    const float* p0 = pred + (size_t)pz * 524288;
    const float* p1 = p0 + 262144;
    const float* t0 = targ + (size_t)pz * 524288;
    const float* t1 = t0 + 262144;

    float lsum = 0.f;

    // ---- prologue: all 256 threads load chunk 0 ----
    for (int idx = tid; idx < CHUNK * IN_W; idx += 256) {
        int r = idx / IN_W, x = idx - r * IN_W;
        int gy = oy - 5 + r, gx = ox - 5 + x;
        float a0 = 0.f, a1 = 0.f, b0 = 0.f, b1 = 0.f;
        if (((unsigned)gy < 512u) && ((unsigned)gx < 512u)) {
            int g = gy * 512 + gx;
            a0 = __ldg(p0 + g); a1 = __ldg(p1 + g);
            b0 = __ldg(t0 + g); b1 = __ldg(t1 + g);
        }
        *reinterpret_cast<ulonglong2*>(inb + r * IN_PITCH + in_off(x)) =
            make_ulonglong2(f2pack(a0, a1), f2pack(b0, b1));
    }
    __syncthreads();

    if (tid < 128) {
        // ================= PRODUCER: h-blur + next-chunk load =================
        const int hr  = tid >> 3;          // row in chunk (0..15)
        const int hx0 = (tid & 7) * 4;     // first output column
        for (int s = 0; s < NCH; s++) {
            const int cs    = s * CHUNK;
            const int nrows = (TOT_R - cs < CHUNK) ? (TOT_R - cs) : CHUNK;
            ull* hb = hbb[s & 1];

            if (hr < nrows) {
                const ull* rp = inb + hr * IN_PITCH;
                ull am1[4], am2[4], asq[4], apt[4];
#pragma unroll
                for (int j = 0; j < 4; j++) { am1[j]=0ULL; am2[j]=0ULL; asq[j]=0ULL; apt[j]=0ULL; }
#pragma unroll
                for (int k = 0; k < 14; k++) {
                    ulonglong2 PT = *reinterpret_cast<const ulonglong2*>(rp + in_off(hx0 + k));
                    ull p = PT.x, t = PT.y;
                    ull sq = f2fma(p, p, f2mul(t, t));
                    ull pt = f2mul(p, t);
#pragma unroll
                    for (int j = 0; j < 4; j++) {
                        const int ki = k - j;
                        if (ki >= 0 && ki <= 10) {
                            ull w = W(ki);
                            am1[j] = f2fma(p,  w, am1[j]);
                            am2[j] = f2fma(t,  w, am2[j]);
                            asq[j] = f2fma(sq, w, asq[j]);
                            apt[j] = f2fma(pt, w, apt[j]);
                        }
                    }
                }
#pragma unroll
                for (int j = 0; j < 4; j++) {
                    int co = hr * HB_PITCH + c_off(hx0 + j);
                    hb[0 * SIG_STRIDE + co] = am1[j];
                    hb[1 * SIG_STRIDE + co] = am2[j];
                    hb[2 * SIG_STRIDE + co] = asq[j];
                    hb[3 * SIG_STRIDE + co] = apt[j];
                }
            }
            BAR_PROD();   // h-reads of inb complete before reload

            if (s + 1 < NCH) {
                const int cs2 = cs + CHUNK;
                const int nr2 = (TOT_R - cs2 < CHUNK) ? (TOT_R - cs2) : CHUNK;
                for (int idx = tid; idx < nr2 * IN_W; idx += 128) {
                    int r = idx / IN_W, x = idx - r * IN_W;
                    int gy = oy - 5 + cs2 + r, gx = ox - 5 + x;
                    float a0 = 0.f, a1 = 0.f, b0 = 0.f, b1 = 0.f;
                    if (((unsigned)gy < 512u) && ((unsigned)gx < 512u)) {
                        int g = gy * 512 + gx;
                        a0 = __ldg(p0 + g); a1 = __ldg(p1 + g);
                        b0 = __ldg(t0 + g); b1 = __ldg(t1 + g);
                    }
                    *reinterpret_cast<ulonglong2*>(inb + r * IN_PITCH + in_off(x)) =
                        make_ulonglong2(f2pack(a0, a1), f2pack(b0, b1));
                }
            }
            BAR_ALL();
        }
    } else {
        // ================= CONSUMER: v shift-register + epilogue =================
        const int ct = tid - 128;
        const int vc = ct & 31;            // column
        const int vs = ct >> 5;            // signal
        ull acc[11];
#pragma unroll
        for (int d = 0; d < 11; d++) acc[d] = 0ULL;

        for (int s = 0; s < NCH; s++) {
            if (s > 0) {
                const int cs    = (s - 1) * CHUNK;
                const int nrows = CHUNK;   // chunks 0..NCH-2 are full
                v_consume(hbb[(s - 1) & 1], acc, ws, vc, vs, ct, cs, nrows, lsum);
            }
            BAR_ALL();
        }
        // last chunk
        {
            const int cs    = (NCH - 1) * CHUNK;
            const int nrows = TOT_R - cs;
            v_consume(hbb[(NCH - 1) & 1], acc, ws, vc, vs, ct, cs, nrows, lsum);
        }
    }

    // --- converged: block reduction -> double atomic + last-block finalize ---
    __syncthreads();
#pragma unroll
    for (int o = 16; o; o >>= 1) lsum += __shfl_xor_sync(0xffffffffu, lsum, o);
    __shared__ float warp_part[8];
    if (lane == 0) warp_part[warp] = lsum;
    __syncthreads();
    if (tid == 0) {
        float v = 0.f;
#pragma unroll
        for (int i = 0; i < 8; i++) v += warp_part[i];
        atomicAdd(&g_acc, (double)v);
        __threadfence();
        unsigned int old = atomicAdd(&g_done, 1u);
        if (old == NBLOCKS - 1u) {
            __threadfence();
            double total = *((volatile double*)&g_acc);
            out[0] = 1.0f - (float)(total * (1.0 / NPIX));
            g_acc  = 0.0;
            g_done = 0u;
        }
    }
}

extern "C" void kernel_launch(void* const* d_in, const int* in_sizes, int n_in,
                              void* d_out, int out_size)
{
    const float* pred = (const float*)d_in[0];
    const float* targ = (const float*)d_in[1];
    const float* win  = (const float*)d_in[2];
    float* out = (float*)d_out;

    const int smem_bytes = (IN_ULL + 2 * HBUF) * 8;   // 48128
    cudaFuncSetAttribute(ssim_main_k, cudaFuncAttributeMaxDynamicSharedMemorySize, smem_bytes);

    dim3 grid(16, 8, 24), blk(256);
    ssim_main_k<<<grid, blk, smem_bytes>>>(pred, targ, win, out);
}

// round 13
// speedup vs baseline: 1.2492x; 1.2492x over previous
#include <cuda_runtime.h>
#include <cstdint>

typedef unsigned long long ull;

// ---------- packed f32x2 helpers ----------
__device__ __forceinline__ ull f2pack(float lo, float hi) {
    ull r; asm("mov.b64 %0,{%1,%2};" : "=l"(r) : "f"(lo), "f"(hi)); return r;
}
__device__ __forceinline__ void f2unpack(ull a, float& lo, float& hi) {
    asm("mov.b64 {%0,%1},%2;" : "=f"(lo), "=f"(hi) : "l"(a));
}
__device__ __forceinline__ ull f2mul(ull a, ull b) {
    ull r; asm("mul.rn.f32x2 %0,%1,%2;" : "=l"(r) : "l"(a), "l"(b)); return r;
}
__device__ __forceinline__ ull f2add(ull a, ull b) {
    ull r; asm("add.rn.f32x2 %0,%1,%2;" : "=l"(r) : "l"(a), "l"(b)); return r;
}
__device__ __forceinline__ ull f2fma(ull a, ull b, ull c) {
    ull r; asm("fma.rn.f32x2 %0,%1,%2,%3;" : "=l"(r) : "l"(a), "l"(b), "l"(c)); return r;
}

#define TW       64                 // tile width (pair cells); 512/64 = 8 exact
#define TH       86                 // tile height; 6 y-tiles (last guarded) -> 1152 CTAs ~ 2 waves
#define IN_W     74                 // TW + 10
#define TOT_R    96                 // TH + 10 input rows
#define CHUNK    15
#define NCH      7                  // 6x15 + 6
#define IN_PITCH 184                // ull per input row ({p,t} 16B cells, swizzled)
#define IN_ULL   (CHUNK * IN_PITCH)     // 2760
#define HB_PITCH 67                 // ull per hb row (8B cells, swizzled)
#define SIG_STRIDE (CHUNK * HB_PITCH)   // 1005
#define HB_ULL   (4 * SIG_STRIDE)       // 4020
#define NPIX     12582912.0         // 48 * 512 * 512
#define NBLOCKS  1152               // 8 x 6 x 24

// swizzles (layouts identical to R10; verified conflict-free)
__device__ __forceinline__ int in_off(int x) { return 2 * x + 2 * (x >> 2); }
__device__ __forceinline__ int c_off(int c)  { return c + (c >> 4); }

// symmetric window: w[d] == w[10-d] (bit-exact on the recovered 1D window)
#define W(d) ws[(d) <= 5 ? (d) : 10 - (d)]

__device__ double        g_acc  = 0.0;
__device__ unsigned int  g_done = 0u;

// dynamic smem: inb[2760] | hb[4020] = 6780 ull = 54240 B -> 4 CTAs/SM
__global__ __launch_bounds__(256, 4) void ssim_main_k(
    const float* __restrict__ pred,
    const float* __restrict__ targ,
    const float* __restrict__ win,
    float* __restrict__ out)
{
    extern __shared__ ull sm[];
    ull* inb = sm;
    ull* hb  = sm + IN_ULL;

    const int tid  = threadIdx.x;
    const int lane = tid & 31;
    const int warp = tid >> 5;

    // --- recover separable symmetric 1D window ---
    float rowsum = 0.f;
#pragma unroll
    for (int j = 0; j < 11; j++) rowsum += __ldg(win + 55 + j);
    const float invr = 1.0f / rowsum;
    ull ws[6];
#pragma unroll
    for (int j = 0; j < 6; j++) {
        float w = __ldg(win + 55 + j) * invr;
        ws[j] = f2pack(w, w);
    }

    const int ox = blockIdx.x * TW;
    const int oy = blockIdx.y * TH;
    const int pz = blockIdx.z;                  // plane pair 0..23
    const float* p0 = pred + (size_t)pz * 524288;
    const float* p1 = p0 + 262144;
    const float* t0 = targ + (size_t)pz * 524288;
    const float* t1 = t0 + 262144;

    // ---- load mapping: thread -> fixed column c, starting row r0, stride 3 ----
    const int lr0   = tid / IN_W;               // 0..3 (r0==3 -> inactive)
    const int lc    = tid - lr0 * IN_W;         // 0..73
    const bool lact = (lr0 < 3);
    const int lgx   = ox - 5 + lc;
    const bool lxin = ((unsigned)lgx < 512u);
    const int linoff = in_off(lc);

    // identities for compute phases
    const int hr   = tid >> 4;                  // h-phase row in chunk (0..15)
    const int hx0  = (tid & 15) * 4;            // h-phase first output column
    const int hkb  = in_off(hx0);               // base swizzle offset (hx0 % 4 == 0)
    const int hcb  = c_off(hx0);                // hb store base ((hx0+j)>>4 == hx0>>4 for j<4)
    const int vc   = tid & 63;                  // v-phase column
    const int vs   = tid >> 6;                  // v-phase signal
    const int ec   = tid & 63;                  // epilogue column (fixed per thread)
    const int ecoff = c_off(ec);
    const int er0  = tid >> 6;                  // epilogue row offset, stride 4

    const ull TWO  = f2pack(2.0f, 2.0f);
    const ull NEG1 = f2pack(-1.0f, -1.0f);
    const ull C1p  = f2pack(1e-4f, 1e-4f);
    const ull C2p  = f2pack(9e-4f, 9e-4f);
    const ull C12p = f2pack(1e-4f + 9e-4f, 1e-4f + 9e-4f);
    const ull EPSp = f2pack(1e-8f, 1e-8f);

    // v sliding shift-register accumulators (persist across chunks)
    ull acc[11];
#pragma unroll
    for (int d = 0; d < 11; d++) acc[d] = 0ULL;

    float lsum = 0.f;

    // ---- initial load: chunk 0 ----
    if (lact) {
        for (int r = lr0; r < CHUNK; r += 3) {
            int gy = oy - 5 + r;
            float a0 = 0.f, a1 = 0.f, b0 = 0.f, b1 = 0.f;
            if (lxin && ((unsigned)gy < 512u)) {
                int g = gy * 512 + lgx;
                a0 = __ldg(p0 + g); a1 = __ldg(p1 + g);
                b0 = __ldg(t0 + g); b1 = __ldg(t1 + g);
            }
            *reinterpret_cast<ulonglong2*>(inb + r * IN_PITCH + linoff) =
                make_ulonglong2(f2pack(a0, a1), f2pack(b0, b1));
        }
    }
    __syncthreads();

    for (int ch = 0; ch < NCH; ch++) {
        const int cs    = ch * CHUNK;
        const int nrows = (TOT_R - cs < CHUNK) ? (TOT_R - cs) : CHUNK;

        // ---- horizontal blur: thread = (row, 4-output x-group) ----
        if (hr < nrows) {
            const ull* rpb = inb + hr * IN_PITCH + hkb;
            ull am1[4], am2[4], asq[4], apt[4];
#pragma unroll
            for (int j = 0; j < 4; j++) { am1[j]=0ULL; am2[j]=0ULL; asq[j]=0ULL; apt[j]=0ULL; }
#pragma unroll
            for (int k = 0; k < 14; k++) {
                // in_off(hx0+k) - in_off(hx0) = 2k + 2(k>>2)  (compile-time)
                ulonglong2 PT = *reinterpret_cast<const ulonglong2*>(rpb + (2 * k + 2 * (k >> 2)));
                ull p = PT.x, t = PT.y;
                ull sq = f2fma(p, p, f2mul(t, t));
                ull pt = f2mul(p, t);
#pragma unroll
                for (int j = 0; j < 4; j++) {
                    const int ki = k - j;
                    if (ki >= 0 && ki <= 10) {
                        ull w = W(ki);
                        am1[j] = f2fma(p,  w, am1[j]);
                        am2[j] = f2fma(t,  w, am2[j]);
                        asq[j] = f2fma(sq, w, asq[j]);
                        apt[j] = f2fma(pt, w, apt[j]);
                    }
                }
            }
#pragma unroll
            for (int j = 0; j < 4; j++) {
                int co = hr * HB_PITCH + hcb + j;
                hb[0 * SIG_STRIDE + co] = am1[j];
                hb[1 * SIG_STRIDE + co] = am2[j];
                hb[2 * SIG_STRIDE + co] = asq[j];
                hb[3 * SIG_STRIDE + co] = apt[j];
            }
        }
        __syncthreads();

        // ---- vertical consume: shift-register; overlay outputs into hb ----
        {
            ull* hs = hb + vs * SIG_STRIDE + c_off(vc);
#pragma unroll
            for (int r = 0; r < CHUNK; r++) {
                if (r < nrows) {
                    ull v = hs[r * HB_PITCH];
#pragma unroll
                    for (int d = 10; d >= 1; d--) acc[d] = f2fma(v, W(d), acc[d - 1]);
                    acc[0] = f2mul(v, W(0));
                    if (cs + r >= 10)
                        hs[r * HB_PITCH] = acc[10];   // slot = r
                }
            }
        }
        __syncthreads();

        // ---- fused phase: epilogue (hb overlay) + load next chunk (inb) ----
        {
            const int e0   = (cs >= 10) ? cs - 10 : 0;
            int e_hi       = cs + nrows - 10;
            const int ymax = 512 - oy;            // fold y-guard into bounds
            if (e_hi > ymax) e_hi = ymax;
            for (int eo = e0 + er0; eo < e_hi; eo += 4) {
                int base = (eo - cs + 10) * HB_PITCH + ecoff;
                ull bm1 = hb[0 * SIG_STRIDE + base];
                ull bm2 = hb[1 * SIG_STRIDE + base];
                ull bsq = hb[2 * SIG_STRIDE + base];
                ull bpt = hb[3 * SIG_STRIDE + base];
                ull m12   = f2mul(bm1, bm2);
                ull den1  = f2fma(bm1, bm1, f2fma(bm2, bm2, C1p));     // mu1^2+mu2^2+C1
                ull den2  = f2fma(den1, NEG1, f2add(bsq, C12p));       // bsq - den1 + C1+C2
                ull sig12 = f2fma(m12,  NEG1, bpt);                    // bpt - m12
                ull num1  = f2fma(m12,   TWO, C1p);
                ull num2  = f2fma(sig12, TWO, C2p);
                ull num   = f2mul(num1, num2);
                ull den   = f2fma(den1, den2, EPSp);
                float n0, n1, d0, d1;
                f2unpack(num, n0, n1);
                f2unpack(den, d0, d1);
                lsum += __fdividef(n0, d0) + __fdividef(n1, d1);
            }
        }

        // load chunk ch+1 into inb
        if (ch < NCH - 1 && lact) {
            const int cs2 = cs + CHUNK;
            const int nr2 = (TOT_R - cs2 < CHUNK) ? (TOT_R - cs2) : CHUNK;
            for (int r = lr0; r < nr2; r += 3) {
                int gy = oy - 5 + cs2 + r;
                float a0 = 0.f, a1 = 0.f, b0 = 0.f, b1 = 0.f;
                if (lxin && ((unsigned)gy < 512u)) {
                    int g = gy * 512 + lgx;
                    a0 = __ldg(p0 + g); a1 = __ldg(p1 + g);
                    b0 = __ldg(t0 + g); b1 = __ldg(t1 + g);
                }
                *reinterpret_cast<ulonglong2*>(inb + r * IN_PITCH + linoff) =
                    make_ulonglong2(f2pack(a0, a1), f2pack(b0, b1));
            }
        }
        __syncthreads();
    }

    // --- block reduction -> double atomic + last-block finalize ---
#pragma unroll
    for (int o = 16; o; o >>= 1) lsum += __shfl_xor_sync(0xffffffffu, lsum, o);
    __shared__ float warp_part[8];
    if (lane == 0) warp_part[warp] = lsum;
    __syncthreads();
    if (tid == 0) {
        float v = 0.f;
#pragma unroll
        for (int i = 0; i < 8; i++) v += warp_part[i];
        atomicAdd(&g_acc, (double)v);
        __threadfence();
        unsigned int old = atomicAdd(&g_done, 1u);
        if (old == NBLOCKS - 1u) {
            __threadfence();
            double total = *((volatile double*)&g_acc);
            out[0] = 1.0f - (float)(total * (1.0 / NPIX));
            g_acc  = 0.0;
            g_done = 0u;
        }
    }
}

extern "C" void kernel_launch(void* const* d_in, const int* in_sizes, int n_in,
                              void* d_out, int out_size)
{
    const float* pred = (const float*)d_in[0];
    const float* targ = (const float*)d_in[1];
    const float* win  = (const float*)d_in[2];
    float* out = (float*)d_out;

    const int smem_bytes = (IN_ULL + HB_ULL) * 8;   // 54240
    cudaFuncSetAttribute(ssim_main_k, cudaFuncAttributeMaxDynamicSharedMemorySize, smem_bytes);

    dim3 grid(8, 6, 24), blk(256);
    ssim_main_k<<<grid, blk, smem_bytes>>>(pred, targ, win, out);
}